// round 9
// baseline (speedup 1.0000x reference)
#include <cuda_runtime.h>
#include <cstdint>

// ---------------------------------------------------------------------------
// GAT (3 layers) on GB300 — fp32 baseline
//   N=50000 nodes, E=400000 edges, H=4 heads, D=64/64/121, Fin=256 each layer
// ---------------------------------------------------------------------------

constexpr int N_ = 50000;
constexpr int E_ = 400000;
constexpr int H_ = 4;

// Scratch (allocation-free: __device__ globals)
__device__ __align__(16) float    g_feat[(size_t)N_ * 484];  // W-projected features
__device__ __align__(16) float    g_agg [(size_t)N_ * 484];  // unnormalized aggregation
__device__ __align__(16) float    g_x   [(size_t)N_ * 256];  // activated layer output
__device__ __align__(16) float    g_e   [(size_t)E_ * H_];   // edge logits, then exp
__device__ float    g_el[N_ * H_];
__device__ float    g_er[N_ * H_];
__device__ unsigned g_mk[N_ * H_];                           // encoded segment max
__device__ float    g_s [N_ * H_];                           // segment sum of exp

// ---- monotone float <-> uint encoding for atomicMax on floats --------------
__device__ __forceinline__ unsigned enc_f(float x) {
    unsigned u = __float_as_uint(x);
    return (u & 0x80000000u) ? ~u : (u | 0x80000000u);
}
__device__ __forceinline__ float dec_f(unsigned k) {
    unsigned u = (k & 0x80000000u) ? (k & 0x7fffffffu) : ~k;
    return __uint_as_float(u);
}

// ---------------------------------------------------------------------------
// Utility kernels
// ---------------------------------------------------------------------------
__global__ void zero4_kernel(float4* __restrict__ p, int n4) {
    int t = blockIdx.x * blockDim.x + threadIdx.x;
    if (t < n4) p[t] = make_float4(0.f, 0.f, 0.f, 0.f);
}

__global__ void init_ms_kernel() {
    int t = blockIdx.x * blockDim.x + threadIdx.x;
    if (t < N_ * H_) { g_mk[t] = 0u; g_s[t] = 0.f; }
}

// ---------------------------------------------------------------------------
// fp32 SIMT GEMM: C[M,Nc] = A[M,K] * B[K,Nc]; K multiple of 16, Nc multiple of 4
// 128x128 tile, BK=16, 256 threads, 8x8 per-thread microtile
// ---------------------------------------------------------------------------
__global__ __launch_bounds__(256) void gemm_kernel(
    const float* __restrict__ A, const float* __restrict__ B, float* __restrict__ C,
    int M, int K, int Nc)
{
    __shared__ float As[16][128];   // [k][m] (transposed)
    __shared__ float Bs[16][128];   // [k][n]

    const int tid = threadIdx.x;
    const int m0 = blockIdx.y * 128;
    const int n0 = blockIdx.x * 128;

    const int ar  = tid >> 2;   // A row within tile (and +64)
    const int ac4 = tid & 3;    // A float4-col within BK
    const int br  = tid >> 5;   // B k-row (and +8)
    const int bc4 = tid & 31;   // B float4-col

    const int ty = tid >> 4;    // 0..15 -> 8-row group
    const int tx = tid & 15;    // 0..15 -> 8-col group

    float acc[8][8];
#pragma unroll
    for (int i = 0; i < 8; i++)
#pragma unroll
        for (int j = 0; j < 8; j++) acc[i][j] = 0.f;

    for (int k0 = 0; k0 < K; k0 += 16) {
        // load A tile (zeros beyond M)
#pragma unroll
        for (int i = 0; i < 2; i++) {
            int r  = ar + i * 64;
            int gm = m0 + r;
            float4 v = make_float4(0.f, 0.f, 0.f, 0.f);
            if (gm < M) v = *(const float4*)(A + (size_t)gm * K + k0 + ac4 * 4);
            As[ac4 * 4 + 0][r] = v.x;
            As[ac4 * 4 + 1][r] = v.y;
            As[ac4 * 4 + 2][r] = v.z;
            As[ac4 * 4 + 3][r] = v.w;
        }
        // load B tile (zeros beyond Nc; Nc % 4 == 0 so float4 never straddles)
#pragma unroll
        for (int i = 0; i < 2; i++) {
            int r  = br + i * 8;
            int gn = n0 + bc4 * 4;
            float4 v = make_float4(0.f, 0.f, 0.f, 0.f);
            if (gn < Nc) v = *(const float4*)(B + (size_t)(k0 + r) * Nc + gn);
            *(float4*)&Bs[r][bc4 * 4] = v;
        }
        __syncthreads();

#pragma unroll
        for (int kk = 0; kk < 16; kk++) {
            float a[8], b[8];
            const float4* ap = (const float4*)&As[kk][ty * 8];
            const float4* bp = (const float4*)&Bs[kk][tx * 8];
            float4 a0 = ap[0], a1 = ap[1];
            float4 b0 = bp[0], b1 = bp[1];
            a[0]=a0.x; a[1]=a0.y; a[2]=a0.z; a[3]=a0.w;
            a[4]=a1.x; a[5]=a1.y; a[6]=a1.z; a[7]=a1.w;
            b[0]=b0.x; b[1]=b0.y; b[2]=b0.z; b[3]=b0.w;
            b[4]=b1.x; b[5]=b1.y; b[6]=b1.z; b[7]=b1.w;
#pragma unroll
            for (int i = 0; i < 8; i++)
#pragma unroll
                for (int j = 0; j < 8; j++)
                    acc[i][j] = fmaf(a[i], b[j], acc[i][j]);
        }
        __syncthreads();
    }

#pragma unroll
    for (int i = 0; i < 8; i++) {
        int gm = m0 + ty * 8 + i;
        if (gm >= M) continue;
#pragma unroll
        for (int j = 0; j < 8; j += 4) {
            int gn = n0 + tx * 8 + j;
            if (gn < Nc)
                *(float4*)(C + (size_t)gm * Nc + gn) =
                    make_float4(acc[i][j], acc[i][j+1], acc[i][j+2], acc[i][j+3]);
        }
    }
}

// ---------------------------------------------------------------------------
// el/er: per (node, head) dot products with attention vectors. Warp per (n,h).
// ---------------------------------------------------------------------------
__global__ void elr_kernel(const float* __restrict__ al, const float* __restrict__ ar, int D) {
    int gw   = (blockIdx.x * blockDim.x + threadIdx.x) >> 5;
    int lane = threadIdx.x & 31;
    if (gw >= N_ * H_) return;
    int n = gw >> 2, h = gw & 3;
    const float* f = g_feat + (size_t)n * (H_ * D) + h * D;
    const float* a = al + h * D;
    const float* b = ar + h * D;
    float sl = 0.f, sr = 0.f;
    for (int d = lane; d < D; d += 32) {
        float v = f[d];
        sl = fmaf(v, a[d], sl);
        sr = fmaf(v, b[d], sr);
    }
#pragma unroll
    for (int o = 16; o; o >>= 1) {
        sl += __shfl_xor_sync(0xffffffffu, sl, o);
        sr += __shfl_xor_sync(0xffffffffu, sr, o);
    }
    if (lane == 0) { g_el[gw] = sl; g_er[gw] = sr; }
}

// ---------------------------------------------------------------------------
// Edge pass A: e = leaky_relu(el[src]+er[dst]); atomicMax segment max.
// ---------------------------------------------------------------------------
__global__ void edge_a_kernel(const int* __restrict__ src, const int* __restrict__ dst) {
    int t = blockIdx.x * blockDim.x + threadIdx.x;
    if (t >= E_ * H_) return;
    int e = t >> 2, h = t & 3;
    int s = src[e], d = dst[e];
    float v = g_el[s * H_ + h] + g_er[d * H_ + h];
    v = (v >= 0.f) ? v : 0.2f * v;
    g_e[t] = v;
    atomicMax(&g_mk[d * H_ + h], enc_f(v));
}

// ---------------------------------------------------------------------------
// Edge pass B: ex = exp(e - max); atomicAdd segment sum.
// ---------------------------------------------------------------------------
__global__ void edge_b_kernel(const int* __restrict__ dst) {
    int t = blockIdx.x * blockDim.x + threadIdx.x;
    if (t >= E_ * H_) return;
    int e = t >> 2, h = t & 3;
    int d = dst[e];
    float m  = dec_f(g_mk[d * H_ + h]);
    float ex = expf(g_e[t] - m);
    g_e[t] = ex;
    atomicAdd(&g_s[d * H_ + h], ex);
}

// ---------------------------------------------------------------------------
// Edge pass C: agg[dst] += ex * feat[src]  (unnormalized). Warp per edge,
// 16B vector reductions (red.global.add.v4.f32) to cut atomic message count 4x.
// ---------------------------------------------------------------------------
template <int D>
__device__ __forceinline__ float pickc(const float4& e, int j) {
    return j < D ? e.x : (j < 2 * D ? e.y : (j < 3 * D ? e.z : e.w));
}

template <int HD, int D>
__global__ void agg_kernel(const int* __restrict__ src, const int* __restrict__ dst) {
    int w    = (blockIdx.x * blockDim.x + threadIdx.x) >> 5;
    int lane = threadIdx.x & 31;
    if (w >= E_) return;
    int s = src[w], d = dst[w];
    float4 ex = *(const float4*)(g_e + (size_t)w * 4);
    const float4* fs = (const float4*)(g_feat + (size_t)s * HD);
    float4*       od = (float4*)(g_agg + (size_t)d * HD);
    constexpr int K4 = HD / 4;
    for (int j4 = lane; j4 < K4; j4 += 32) {
        float4 f = fs[j4];
        int j = j4 * 4;
        float4 v;
        v.x = f.x * pickc<D>(ex, j + 0);
        v.y = f.y * pickc<D>(ex, j + 1);
        v.z = f.z * pickc<D>(ex, j + 2);
        v.w = f.w * pickc<D>(ex, j + 3);
        asm volatile("red.global.add.v4.f32 [%0], {%1,%2,%3,%4};"
                     :: "l"(od + j4), "f"(v.x), "f"(v.y), "f"(v.z), "f"(v.w)
                     : "memory");
    }
}

// ---------------------------------------------------------------------------
// Epilogues: normalize by segment sum (0 for isolated nodes, matching JAX),
// then ELU (layers 1/2 -> g_x) or head-mean (layer 3 -> d_out).
// ---------------------------------------------------------------------------
__global__ void fin12_kernel() {
    int t = blockIdx.x * blockDim.x + threadIdx.x;
    if (t >= N_ * 256) return;
    int n = t >> 8;
    int h = (t >> 6) & 3;
    float sv = g_s[n * H_ + h];
    float v  = (sv > 0.f) ? g_agg[t] / sv : 0.f;
    g_x[t] = (v > 0.f) ? v : expm1f(v);
}

__global__ void fin3_kernel(float* __restrict__ out) {
    int t = blockIdx.x * blockDim.x + threadIdx.x;
    if (t >= N_ * 121) return;
    int n = t / 121;
    int c = t - n * 121;
    float acc = 0.f;
#pragma unroll
    for (int h = 0; h < 4; h++) {
        float sv = g_s[n * H_ + h];
        if (sv > 0.f) acc += g_agg[(size_t)n * 484 + h * 121 + c] / sv;
    }
    out[t] = acc * 0.25f;
}

// ---------------------------------------------------------------------------
// Launch
// ---------------------------------------------------------------------------
extern "C" void kernel_launch(void* const* d_in, const int* in_sizes, int n_in,
                              void* d_out, int out_size)
{
    const float* h   = (const float*)d_in[0];
    const int*   src = (const int*)d_in[1];
    const int*   dst = (const int*)d_in[2];
    const float* W [3] = {(const float*)d_in[3], (const float*)d_in[6], (const float*)d_in[9]};
    const float* al[3] = {(const float*)d_in[4], (const float*)d_in[7], (const float*)d_in[10]};
    const float* ar[3] = {(const float*)d_in[5], (const float*)d_in[8], (const float*)d_in[11]};
    float* out = (float*)d_out;

    void* p;
    cudaGetSymbolAddress(&p, g_feat); float* feat = (float*)p;
    cudaGetSymbolAddress(&p, g_agg);  float* agg  = (float*)p;
    cudaGetSymbolAddress(&p, g_x);    float* x    = (float*)p;

    const int T = 256;

    for (int L = 0; L < 3; L++) {
        const int HD = (L == 2) ? 484 : 256;
        const int D  = (L == 2) ? 121 : 64;
        const float* A = (L == 0) ? h : x;

        // clear aggregation buffer + segment max/sum
        int n4 = N_ * HD / 4;
        zero4_kernel<<<(n4 + T - 1) / T, T>>>((float4*)agg, n4);
        init_ms_kernel<<<(N_ * H_ + T - 1) / T, T>>>();

        // feat = A @ W
        dim3 gg((HD + 127) / 128, (N_ + 127) / 128);
        gemm_kernel<<<gg, T>>>(A, W[L], feat, N_, 256, HD);

        // attention logits per node
        elr_kernel<<<((N_ * H_ * 32) + T - 1) / T, T>>>(al[L], ar[L], D);

        // edge softmax pieces
        edge_a_kernel<<<(E_ * H_ + T - 1) / T, T>>>(src, dst);
        edge_b_kernel<<<(E_ * H_ + T - 1) / T, T>>>(dst);

        // scatter-aggregate
        if (L == 2) agg_kernel<484, 121><<<((E_ * 32) + T - 1) / T, T>>>(src, dst);
        else        agg_kernel<256, 64 ><<<((E_ * 32) + T - 1) / T, T>>>(src, dst);

        // epilogue
        if (L == 2) fin3_kernel<<<(N_ * 121 + T - 1) / T, T>>>(out);
        else        fin12_kernel<<<(N_ * 256 + T - 1) / T, T>>>();
    }
}

// round 10
// speedup vs baseline: 1.0027x; 1.0027x over previous
#include <cuda_runtime.h>
#include <cstdint>

// ---------------------------------------------------------------------------
// GAT (3 layers) on GB300 — TF32x3 tensor-core GEMM + fp32 edge pipeline
//   N=50000 nodes, E=400000 edges, H=4 heads, D=64/64/121, Fin=256 each layer
// ---------------------------------------------------------------------------

constexpr int N_ = 50000;
constexpr int E_ = 400000;
constexpr int H_ = 4;

// Scratch (allocation-free: __device__ globals)
__device__ __align__(16) float    g_feat[(size_t)N_ * 484];  // W-projected features
__device__ __align__(16) float    g_agg [(size_t)N_ * 484];  // unnormalized aggregation
__device__ __align__(16) float    g_x   [(size_t)N_ * 256];  // activated layer output
__device__ __align__(16) float    g_e   [(size_t)E_ * H_];   // edge logits, then exp
__device__ float    g_el[N_ * H_];
__device__ float    g_er[N_ * H_];
__device__ unsigned g_mk[N_ * H_];                           // encoded segment max
__device__ float    g_s [N_ * H_];                           // segment sum of exp

// ---- monotone float <-> uint encoding for atomicMax on floats --------------
__device__ __forceinline__ unsigned enc_f(float x) {
    unsigned u = __float_as_uint(x);
    return (u & 0x80000000u) ? ~u : (u | 0x80000000u);
}
__device__ __forceinline__ float dec_f(unsigned k) {
    unsigned u = (k & 0x80000000u) ? (k & 0x7fffffffu) : ~k;
    return __uint_as_float(u);
}

// ---------------------------------------------------------------------------
// Utility kernels
// ---------------------------------------------------------------------------
__global__ void zero4_kernel(float4* __restrict__ p, int n4) {
    int t = blockIdx.x * blockDim.x + threadIdx.x;
    if (t < n4) p[t] = make_float4(0.f, 0.f, 0.f, 0.f);
}

__global__ void init_ms_kernel() {
    int t = blockIdx.x * blockDim.x + threadIdx.x;
    if (t < N_ * H_) { g_mk[t] = 0u; g_s[t] = 0.f; }
}

// ---------------------------------------------------------------------------
// TF32x3 tensor-core GEMM: C[M,Nc] = A[M,256] * B[256,Nc]
// Block tile 128x128, BK=32, 256 threads (8 warps, each 64x32).
// 3xTF32: split x = hi + lo (both tf32); D += Ahi*Bhi + Alo*Bhi + Ahi*Blo
// => ~fp32 accuracy at 3x tensor throughput cost.
// ---------------------------------------------------------------------------
__device__ __forceinline__ void split_tf32(float x, unsigned& hi, unsigned& lo) {
    asm("cvt.rna.tf32.f32 %0, %1;" : "=r"(hi) : "f"(x));
    float r = x - __uint_as_float(hi);
    asm("cvt.rna.tf32.f32 %0, %1;" : "=r"(lo) : "f"(r));
}

__device__ __forceinline__ void mma_tf32(float c[4], const unsigned a[4],
                                         unsigned b0, unsigned b1) {
    asm volatile(
        "mma.sync.aligned.m16n8k8.row.col.f32.tf32.tf32.f32 "
        "{%0,%1,%2,%3}, {%4,%5,%6,%7}, {%8,%9}, {%0,%1,%2,%3};"
        : "+f"(c[0]), "+f"(c[1]), "+f"(c[2]), "+f"(c[3])
        : "r"(a[0]), "r"(a[1]), "r"(a[2]), "r"(a[3]), "r"(b0), "r"(b1));
}

__global__ __launch_bounds__(256) void gemm_tf32_kernel(
    const float* __restrict__ A, const float* __restrict__ B, float* __restrict__ C,
    int M, int Nc)
{
    constexpr int K = 256, BM = 128, BN = 128, BK = 32;
    __shared__ float As[BK][BM + 4];   // [k][m]
    __shared__ float Bs[BK][BN + 4];   // [k][n]

    const int tid  = threadIdx.x;
    const int lane = tid & 31;
    const int wid  = tid >> 5;
    const int gid  = lane >> 2;    // 0..7
    const int tig  = lane & 3;     // 0..3
    const int wm   = (wid & 1) * 64;
    const int wn   = (wid >> 1) * 32;
    const int m0   = blockIdx.y * BM;
    const int n0   = blockIdx.x * BN;

    float c[4][4][4];
#pragma unroll
    for (int i = 0; i < 4; i++)
#pragma unroll
        for (int j = 0; j < 4; j++)
#pragma unroll
            for (int k = 0; k < 4; k++) c[i][j][k] = 0.f;

    for (int k0 = 0; k0 < K; k0 += BK) {
        // A tile: 128 rows x 32 k-cols, transposed into As[k][m]
#pragma unroll
        for (int r = 0; r < 4; r++) {
            int i   = tid + r * 256;        // 0..1023 float4s
            int row = i >> 3;
            int c4  = (i & 7) * 4;
            int gm  = m0 + row;
            float4 v = make_float4(0.f, 0.f, 0.f, 0.f);
            if (gm < M) v = *(const float4*)(A + (size_t)gm * K + k0 + c4);
            As[c4 + 0][row] = v.x;
            As[c4 + 1][row] = v.y;
            As[c4 + 2][row] = v.z;
            As[c4 + 3][row] = v.w;
        }
        // B tile: 32 k-rows x 128 cols, direct into Bs[k][n]
#pragma unroll
        for (int r = 0; r < 4; r++) {
            int i   = tid + r * 256;
            int row = i >> 5;
            int c4  = (i & 31) * 4;
            int gn  = n0 + c4;
            float4 v = make_float4(0.f, 0.f, 0.f, 0.f);
            if (gn < Nc) v = *(const float4*)(B + (size_t)(k0 + row) * Nc + gn);
            *(float4*)&Bs[row][c4] = v;
        }
        __syncthreads();

#pragma unroll
        for (int kk = 0; kk < BK; kk += 8) {
            // A fragments (hi+lo) for the 4 m-tiles of this warp
            unsigned ahi[4][4], alo[4][4];
#pragma unroll
            for (int mt = 0; mt < 4; mt++) {
                int r0 = wm + mt * 16 + gid;
                float x0 = As[kk + tig    ][r0];
                float x1 = As[kk + tig    ][r0 + 8];
                float x2 = As[kk + tig + 4][r0];
                float x3 = As[kk + tig + 4][r0 + 8];
                split_tf32(x0, ahi[mt][0], alo[mt][0]);
                split_tf32(x1, ahi[mt][1], alo[mt][1]);
                split_tf32(x2, ahi[mt][2], alo[mt][2]);
                split_tf32(x3, ahi[mt][3], alo[mt][3]);
            }
#pragma unroll
            for (int nt = 0; nt < 4; nt++) {
                int cn = wn + nt * 8 + gid;
                float y0 = Bs[kk + tig    ][cn];
                float y1 = Bs[kk + tig + 4][cn];
                unsigned bh0, bl0, bh1, bl1;
                split_tf32(y0, bh0, bl0);
                split_tf32(y1, bh1, bl1);
#pragma unroll
                for (int mt = 0; mt < 4; mt++) {
                    mma_tf32(c[mt][nt], alo[mt], bh0, bh1);
                    mma_tf32(c[mt][nt], ahi[mt], bl0, bl1);
                    mma_tf32(c[mt][nt], ahi[mt], bh0, bh1);
                }
            }
        }
        __syncthreads();
    }

    // Epilogue: c0,c1 -> (row gid, cols tig*2, tig*2+1); c2,c3 -> row gid+8
#pragma unroll
    for (int mt = 0; mt < 4; mt++) {
        int r0 = m0 + wm + mt * 16 + gid;
#pragma unroll
        for (int nt = 0; nt < 4; nt++) {
            int cn = n0 + wn + nt * 8 + tig * 2;
            if (cn < Nc) {   // cn even, Nc even -> pair fully in-bounds
                if (r0 < M)
                    *(float2*)(C + (size_t)r0 * Nc + cn) =
                        make_float2(c[mt][nt][0], c[mt][nt][1]);
                if (r0 + 8 < M)
                    *(float2*)(C + (size_t)(r0 + 8) * Nc + cn) =
                        make_float2(c[mt][nt][2], c[mt][nt][3]);
            }
        }
    }
}

// ---------------------------------------------------------------------------
// el/er: per (node, head) dot products with attention vectors. Warp per (n,h).
// ---------------------------------------------------------------------------
__global__ void elr_kernel(const float* __restrict__ al, const float* __restrict__ ar, int D) {
    int gw   = (blockIdx.x * blockDim.x + threadIdx.x) >> 5;
    int lane = threadIdx.x & 31;
    if (gw >= N_ * H_) return;
    int n = gw >> 2, h = gw & 3;
    const float* f = g_feat + (size_t)n * (H_ * D) + h * D;
    const float* a = al + h * D;
    const float* b = ar + h * D;
    float sl = 0.f, sr = 0.f;
    for (int d = lane; d < D; d += 32) {
        float v = f[d];
        sl = fmaf(v, a[d], sl);
        sr = fmaf(v, b[d], sr);
    }
#pragma unroll
    for (int o = 16; o; o >>= 1) {
        sl += __shfl_xor_sync(0xffffffffu, sl, o);
        sr += __shfl_xor_sync(0xffffffffu, sr, o);
    }
    if (lane == 0) { g_el[gw] = sl; g_er[gw] = sr; }
}

// ---------------------------------------------------------------------------
// Edge pass A: e = leaky_relu(el[src]+er[dst]); atomicMax segment max.
// ---------------------------------------------------------------------------
__global__ void edge_a_kernel(const int* __restrict__ src, const int* __restrict__ dst) {
    int t = blockIdx.x * blockDim.x + threadIdx.x;
    if (t >= E_ * H_) return;
    int e = t >> 2, h = t & 3;
    int s = src[e], d = dst[e];
    float v = g_el[s * H_ + h] + g_er[d * H_ + h];
    v = (v >= 0.f) ? v : 0.2f * v;
    g_e[t] = v;
    atomicMax(&g_mk[d * H_ + h], enc_f(v));
}

// ---------------------------------------------------------------------------
// Edge pass B: ex = exp(e - max); atomicAdd segment sum.
// ---------------------------------------------------------------------------
__global__ void edge_b_kernel(const int* __restrict__ dst) {
    int t = blockIdx.x * blockDim.x + threadIdx.x;
    if (t >= E_ * H_) return;
    int e = t >> 2, h = t & 3;
    int d = dst[e];
    float m  = dec_f(g_mk[d * H_ + h]);
    float ex = expf(g_e[t] - m);
    g_e[t] = ex;
    atomicAdd(&g_s[d * H_ + h], ex);
}

// ---------------------------------------------------------------------------
// Edge pass C: agg[dst] += ex * feat[src]  (unnormalized). Warp per edge,
// 16B vector reductions (red.global.add.v4.f32) to cut atomic message count 4x.
// ---------------------------------------------------------------------------
template <int D>
__device__ __forceinline__ float pickc(const float4& e, int j) {
    return j < D ? e.x : (j < 2 * D ? e.y : (j < 3 * D ? e.z : e.w));
}

template <int HD, int D>
__global__ void agg_kernel(const int* __restrict__ src, const int* __restrict__ dst) {
    int w    = (blockIdx.x * blockDim.x + threadIdx.x) >> 5;
    int lane = threadIdx.x & 31;
    if (w >= E_) return;
    int s = src[w], d = dst[w];
    float4 ex = *(const float4*)(g_e + (size_t)w * 4);
    const float4* fs = (const float4*)(g_feat + (size_t)s * HD);
    float4*       od = (float4*)(g_agg + (size_t)d * HD);
    constexpr int K4 = HD / 4;
    for (int j4 = lane; j4 < K4; j4 += 32) {
        float4 f = fs[j4];
        int j = j4 * 4;
        float4 v;
        v.x = f.x * pickc<D>(ex, j + 0);
        v.y = f.y * pickc<D>(ex, j + 1);
        v.z = f.z * pickc<D>(ex, j + 2);
        v.w = f.w * pickc<D>(ex, j + 3);
        asm volatile("red.global.add.v4.f32 [%0], {%1,%2,%3,%4};"
                     :: "l"(od + j4), "f"(v.x), "f"(v.y), "f"(v.z), "f"(v.w)
                     : "memory");
    }
}

// ---------------------------------------------------------------------------
// Epilogues: normalize by segment sum (0 for isolated nodes, matching JAX),
// then ELU (layers 1/2 -> g_x) or head-mean (layer 3 -> d_out).
// ---------------------------------------------------------------------------
__global__ void fin12_kernel() {
    int t = blockIdx.x * blockDim.x + threadIdx.x;
    if (t >= N_ * 256) return;
    int n = t >> 8;
    int h = (t >> 6) & 3;
    float sv = g_s[n * H_ + h];
    float v  = (sv > 0.f) ? g_agg[t] / sv : 0.f;
    g_x[t] = (v > 0.f) ? v : expm1f(v);
}

__global__ void fin3_kernel(float* __restrict__ out) {
    int t = blockIdx.x * blockDim.x + threadIdx.x;
    if (t >= N_ * 121) return;
    int n = t / 121;
    int c = t - n * 121;
    float acc = 0.f;
#pragma unroll
    for (int h = 0; h < 4; h++) {
        float sv = g_s[n * H_ + h];
        if (sv > 0.f) acc += g_agg[(size_t)n * 484 + h * 121 + c] / sv;
    }
    out[t] = acc * 0.25f;
}

// ---------------------------------------------------------------------------
// Launch
// ---------------------------------------------------------------------------
extern "C" void kernel_launch(void* const* d_in, const int* in_sizes, int n_in,
                              void* d_out, int out_size)
{
    const float* h   = (const float*)d_in[0];
    const int*   src = (const int*)d_in[1];
    const int*   dst = (const int*)d_in[2];
    const float* W [3] = {(const float*)d_in[3], (const float*)d_in[6], (const float*)d_in[9]};
    const float* al[3] = {(const float*)d_in[4], (const float*)d_in[7], (const float*)d_in[10]};
    const float* ar[3] = {(const float*)d_in[5], (const float*)d_in[8], (const float*)d_in[11]};
    float* out = (float*)d_out;

    void* p;
    cudaGetSymbolAddress(&p, g_feat); float* feat = (float*)p;
    cudaGetSymbolAddress(&p, g_agg);  float* agg  = (float*)p;
    cudaGetSymbolAddress(&p, g_x);    float* x    = (float*)p;

    const int T = 256;

    for (int L = 0; L < 3; L++) {
        const int HD = (L == 2) ? 484 : 256;
        const int D  = (L == 2) ? 121 : 64;
        const float* A = (L == 0) ? h : x;

        // clear aggregation buffer + segment max/sum
        int n4 = N_ * HD / 4;
        zero4_kernel<<<(n4 + T - 1) / T, T>>>((float4*)agg, n4);
        init_ms_kernel<<<(N_ * H_ + T - 1) / T, T>>>();

        // feat = A @ W   (TF32x3 tensor cores)
        dim3 gg((HD + 127) / 128, (N_ + 127) / 128);
        gemm_tf32_kernel<<<gg, T>>>(A, W[L], feat, N_, HD);

        // attention logits per node
        elr_kernel<<<((N_ * H_ * 32) + T - 1) / T, T>>>(al[L], ar[L], D);

        // edge softmax pieces
        edge_a_kernel<<<(E_ * H_ + T - 1) / T, T>>>(src, dst);
        edge_b_kernel<<<(E_ * H_ + T - 1) / T, T>>>(dst);

        // scatter-aggregate
        if (L == 2) agg_kernel<484, 121><<<((E_ * 32) + T - 1) / T, T>>>(src, dst);
        else        agg_kernel<256, 64 ><<<((E_ * 32) + T - 1) / T, T>>>(src, dst);

        // epilogue
        if (L == 2) fin3_kernel<<<(N_ * 121 + T - 1) / T, T>>>(out);
        else        fin12_kernel<<<(N_ * 256 + T - 1) / T, T>>>();
    }
}

// round 11
// speedup vs baseline: 1.3700x; 1.3664x over previous
#include <cuda_runtime.h>
#include <cstdint>

// ---------------------------------------------------------------------------
// GAT (3 layers) on GB300 — TF32x3 tensor-core GEMM + gather-based edge softmax
//   N=50000 nodes, E=400000 edges, H=4 heads, D=64/64/121, Fin=256 each layer
//   Aggregation: warp-per-dst gather over per-dst src buckets (avg degree 8).
//   No atomics in the per-layer path.
// ---------------------------------------------------------------------------

constexpr int N_   = 50000;
constexpr int E_   = 400000;
constexpr int H_   = 4;
constexpr int CAP_ = 64;     // bucket capacity per dst (Poisson(8); P(>64) ~ 0)

// Scratch (allocation-free: __device__ globals)
__device__ __align__(16) float g_feat[(size_t)N_ * 484];  // W-projected features
__device__ __align__(16) float g_x   [(size_t)N_ * 256];  // activated layer output
__device__ __align__(16) float g_el  [N_ * H_];
__device__ __align__(16) float g_er  [N_ * H_];
__device__ int  g_deg[N_];
__device__ int  g_bkt[(size_t)N_ * CAP_];                 // src ids grouped by dst

// ---------------------------------------------------------------------------
// Utility
// ---------------------------------------------------------------------------
__global__ void zero4_kernel(float4* __restrict__ p, int n4) {
    int t = blockIdx.x * blockDim.x + threadIdx.x;
    if (t < n4) p[t] = make_float4(0.f, 0.f, 0.f, 0.f);
}

__global__ void deg_zero_kernel() {
    int t = blockIdx.x * blockDim.x + threadIdx.x;
    if (t < N_) g_deg[t] = 0;
}

__global__ void scatter_kernel(const int* __restrict__ src, const int* __restrict__ dst) {
    int e = blockIdx.x * blockDim.x + threadIdx.x;
    if (e >= E_) return;
    int d = dst[e];
    int slot = atomicAdd(&g_deg[d], 1);
    if (slot < CAP_) g_bkt[(size_t)d * CAP_ + slot] = src[e];
}

// ---------------------------------------------------------------------------
// TF32x3 tensor-core GEMM: C[M,Nc] = A[M,256] * B[256,Nc]
// Block tile 128x128, BK=32, 256 threads (8 warps, each 64x32).
// ---------------------------------------------------------------------------
__device__ __forceinline__ void split_tf32(float x, unsigned& hi, unsigned& lo) {
    asm("cvt.rna.tf32.f32 %0, %1;" : "=r"(hi) : "f"(x));
    float r = x - __uint_as_float(hi);
    asm("cvt.rna.tf32.f32 %0, %1;" : "=r"(lo) : "f"(r));
}

__device__ __forceinline__ void mma_tf32(float c[4], const unsigned a[4],
                                         unsigned b0, unsigned b1) {
    asm volatile(
        "mma.sync.aligned.m16n8k8.row.col.f32.tf32.tf32.f32 "
        "{%0,%1,%2,%3}, {%4,%5,%6,%7}, {%8,%9}, {%0,%1,%2,%3};"
        : "+f"(c[0]), "+f"(c[1]), "+f"(c[2]), "+f"(c[3])
        : "r"(a[0]), "r"(a[1]), "r"(a[2]), "r"(a[3]), "r"(b0), "r"(b1));
}

__global__ __launch_bounds__(256) void gemm_tf32_kernel(
    const float* __restrict__ A, const float* __restrict__ B, float* __restrict__ C,
    int M, int Nc)
{
    constexpr int K = 256, BM = 128, BN = 128, BK = 32;
    __shared__ float As[BK][BM + 4];   // [k][m]
    __shared__ float Bs[BK][BN + 4];   // [k][n]

    const int tid  = threadIdx.x;
    const int lane = tid & 31;
    const int wid  = tid >> 5;
    const int gid  = lane >> 2;    // 0..7
    const int tig  = lane & 3;     // 0..3
    const int wm   = (wid & 1) * 64;
    const int wn   = (wid >> 1) * 32;
    const int m0   = blockIdx.y * BM;
    const int n0   = blockIdx.x * BN;

    float c[4][4][4];
#pragma unroll
    for (int i = 0; i < 4; i++)
#pragma unroll
        for (int j = 0; j < 4; j++)
#pragma unroll
            for (int k = 0; k < 4; k++) c[i][j][k] = 0.f;

    for (int k0 = 0; k0 < K; k0 += BK) {
#pragma unroll
        for (int r = 0; r < 4; r++) {
            int i   = tid + r * 256;
            int row = i >> 3;
            int c4  = (i & 7) * 4;
            int gm  = m0 + row;
            float4 v = make_float4(0.f, 0.f, 0.f, 0.f);
            if (gm < M) v = *(const float4*)(A + (size_t)gm * K + k0 + c4);
            As[c4 + 0][row] = v.x;
            As[c4 + 1][row] = v.y;
            As[c4 + 2][row] = v.z;
            As[c4 + 3][row] = v.w;
        }
#pragma unroll
        for (int r = 0; r < 4; r++) {
            int i   = tid + r * 256;
            int row = i >> 5;
            int c4  = (i & 31) * 4;
            int gn  = n0 + c4;
            float4 v = make_float4(0.f, 0.f, 0.f, 0.f);
            if (gn < Nc) v = *(const float4*)(B + (size_t)(k0 + row) * Nc + gn);
            *(float4*)&Bs[row][c4] = v;
        }
        __syncthreads();

#pragma unroll
        for (int kk = 0; kk < BK; kk += 8) {
            unsigned ahi[4][4], alo[4][4];
#pragma unroll
            for (int mt = 0; mt < 4; mt++) {
                int r0 = wm + mt * 16 + gid;
                float x0 = As[kk + tig    ][r0];
                float x1 = As[kk + tig    ][r0 + 8];
                float x2 = As[kk + tig + 4][r0];
                float x3 = As[kk + tig + 4][r0 + 8];
                split_tf32(x0, ahi[mt][0], alo[mt][0]);
                split_tf32(x1, ahi[mt][1], alo[mt][1]);
                split_tf32(x2, ahi[mt][2], alo[mt][2]);
                split_tf32(x3, ahi[mt][3], alo[mt][3]);
            }
#pragma unroll
            for (int nt = 0; nt < 4; nt++) {
                int cn = wn + nt * 8 + gid;
                float y0 = Bs[kk + tig    ][cn];
                float y1 = Bs[kk + tig + 4][cn];
                unsigned bh0, bl0, bh1, bl1;
                split_tf32(y0, bh0, bl0);
                split_tf32(y1, bh1, bl1);
#pragma unroll
                for (int mt = 0; mt < 4; mt++) {
                    mma_tf32(c[mt][nt], alo[mt], bh0, bh1);
                    mma_tf32(c[mt][nt], ahi[mt], bl0, bl1);
                    mma_tf32(c[mt][nt], ahi[mt], bh0, bh1);
                }
            }
        }
        __syncthreads();
    }

#pragma unroll
    for (int mt = 0; mt < 4; mt++) {
        int r0 = m0 + wm + mt * 16 + gid;
#pragma unroll
        for (int nt = 0; nt < 4; nt++) {
            int cn = n0 + wn + nt * 8 + tig * 2;
            if (cn < Nc) {
                if (r0 < M)
                    *(float2*)(C + (size_t)r0 * Nc + cn) =
                        make_float2(c[mt][nt][0], c[mt][nt][1]);
                if (r0 + 8 < M)
                    *(float2*)(C + (size_t)(r0 + 8) * Nc + cn) =
                        make_float2(c[mt][nt][2], c[mt][nt][3]);
            }
        }
    }
}

// ---------------------------------------------------------------------------
// el/er: per (node, head) dot products with attention vectors. Warp per (n,h).
// ---------------------------------------------------------------------------
__global__ void elr_kernel(const float* __restrict__ al, const float* __restrict__ ar, int D) {
    int gw   = (blockIdx.x * blockDim.x + threadIdx.x) >> 5;
    int lane = threadIdx.x & 31;
    if (gw >= N_ * H_) return;
    int n = gw >> 2, h = gw & 3;
    const float* f = g_feat + (size_t)n * (H_ * D) + h * D;
    const float* a = al + h * D;
    const float* b = ar + h * D;
    float sl = 0.f, sr = 0.f;
    for (int d = lane; d < D; d += 32) {
        float v = f[d];
        sl = fmaf(v, a[d], sl);
        sr = fmaf(v, b[d], sr);
    }
#pragma unroll
    for (int o = 16; o; o >>= 1) {
        sl += __shfl_xor_sync(0xffffffffu, sl, o);
        sr += __shfl_xor_sync(0xffffffffu, sr, o);
    }
    if (lane == 0) { g_el[gw] = sl; g_er[gw] = sr; }
}

// ---------------------------------------------------------------------------
// Warp-reduce helpers
// ---------------------------------------------------------------------------
__device__ __forceinline__ float wmax(float v) {
#pragma unroll
    for (int o = 16; o; o >>= 1) v = fmaxf(v, __shfl_xor_sync(0xffffffffu, v, o));
    return v;
}
__device__ __forceinline__ float wsum(float v) {
#pragma unroll
    for (int o = 16; o; o >>= 1) v += __shfl_xor_sync(0xffffffffu, v, o);
    return v;
}

// ---------------------------------------------------------------------------
// Fused gather kernel, layers 1/2 (HD=256, D=64): warp per dst node.
// Computes edge softmax + weighted aggregation + ELU, writes g_x.
// ---------------------------------------------------------------------------
__global__ __launch_bounds__(256) void gat_gather256_kernel() {
    const int d    = (blockIdx.x * blockDim.x + threadIdx.x) >> 5;
    const int lane = threadIdx.x & 31;
    if (d >= N_) return;

    float* out = g_x + (size_t)d * 256;
    int deg = g_deg[d];
    if (deg > CAP_) deg = CAP_;

    if (deg == 0) {
        *(float4*)(out + lane * 4)         = make_float4(0.f, 0.f, 0.f, 0.f);
        *(float4*)(out + 128 + lane * 4)   = make_float4(0.f, 0.f, 0.f, 0.f);
        return;
    }

    // ---- phase 1: per-edge logits and softmax weights (lane i = edge i) ----
    const float NEG = -3.0e38f;
    float4 erv = *(const float4*)(g_el + 0 * 0 + (size_t)d * 4 + 0 * 0), dummy;
    (void)dummy;
    erv = *(const float4*)(g_er + (size_t)d * 4);
    int   s  = 0;
    float e0 = NEG, e1 = NEG, e2 = NEG, e3 = NEG;
    if (lane < deg) {
        s = g_bkt[(size_t)d * CAP_ + lane];
        float4 elv = *(const float4*)(g_el + (size_t)s * 4);
        e0 = elv.x + erv.x; e0 = (e0 >= 0.f) ? e0 : 0.2f * e0;
        e1 = elv.y + erv.y; e1 = (e1 >= 0.f) ? e1 : 0.2f * e1;
        e2 = elv.z + erv.z; e2 = (e2 >= 0.f) ? e2 : 0.2f * e2;
        e3 = elv.w + erv.w; e3 = (e3 >= 0.f) ? e3 : 0.2f * e3;
    }
    float m0 = wmax(e0), m1 = wmax(e1), m2 = wmax(e2), m3 = wmax(e3);
    float x0 = (lane < deg) ? expf(e0 - m0) : 0.f;
    float x1 = (lane < deg) ? expf(e1 - m1) : 0.f;
    float x2 = (lane < deg) ? expf(e2 - m2) : 0.f;
    float x3 = (lane < deg) ? expf(e3 - m3) : 0.f;
    float a0 = x0 / wsum(x0);
    float a1 = x1 / wsum(x1);
    float a2 = x2 / wsum(x2);
    float a3 = x3 / wsum(x3);

    // ---- phase 2: weighted feature accumulation ----
    // lane covers float4 j4=lane (head lane/16) and j4=lane+32 (head 2+lane/16)
    float4 acc0 = make_float4(0.f, 0.f, 0.f, 0.f);
    float4 acc1 = make_float4(0.f, 0.f, 0.f, 0.f);
    const bool hi16 = (lane >= 16);

    for (int i = 0; i < deg; i++) {
        int   si = __shfl_sync(0xffffffffu, s, i);
        float b0 = __shfl_sync(0xffffffffu, a0, i);
        float b1 = __shfl_sync(0xffffffffu, a1, i);
        float b2 = __shfl_sync(0xffffffffu, a2, i);
        float b3 = __shfl_sync(0xffffffffu, a3, i);
        float wa = hi16 ? b1 : b0;
        float wb = hi16 ? b3 : b2;
        const float* F = g_feat + (size_t)si * 256;
        float4 f0 = *(const float4*)(F + lane * 4);
        float4 f1 = *(const float4*)(F + 128 + lane * 4);
        acc0.x = fmaf(wa, f0.x, acc0.x); acc0.y = fmaf(wa, f0.y, acc0.y);
        acc0.z = fmaf(wa, f0.z, acc0.z); acc0.w = fmaf(wa, f0.w, acc0.w);
        acc1.x = fmaf(wb, f1.x, acc1.x); acc1.y = fmaf(wb, f1.y, acc1.y);
        acc1.z = fmaf(wb, f1.z, acc1.z); acc1.w = fmaf(wb, f1.w, acc1.w);
    }

    // ---- ELU + store ----
    float4 o0, o1;
    o0.x = acc0.x > 0.f ? acc0.x : expm1f(acc0.x);
    o0.y = acc0.y > 0.f ? acc0.y : expm1f(acc0.y);
    o0.z = acc0.z > 0.f ? acc0.z : expm1f(acc0.z);
    o0.w = acc0.w > 0.f ? acc0.w : expm1f(acc0.w);
    o1.x = acc1.x > 0.f ? acc1.x : expm1f(acc1.x);
    o1.y = acc1.y > 0.f ? acc1.y : expm1f(acc1.y);
    o1.z = acc1.z > 0.f ? acc1.z : expm1f(acc1.z);
    o1.w = acc1.w > 0.f ? acc1.w : expm1f(acc1.w);
    *(float4*)(out + lane * 4)       = o0;
    *(float4*)(out + 128 + lane * 4) = o1;
}

// ---------------------------------------------------------------------------
// Fused gather kernel, layer 3 (HD=484, D=121): warp per dst node.
// Softmax + aggregation + head-mean (via smem transpose), writes d_out.
// ---------------------------------------------------------------------------
__global__ __launch_bounds__(256) void gat_gather484_kernel(float* __restrict__ outp) {
    __shared__ float sm[8][484];
    const int d    = (blockIdx.x * blockDim.x + threadIdx.x) >> 5;
    const int lane = threadIdx.x & 31;
    const int warp = (threadIdx.x >> 5);
    if (d >= N_) return;

    float* out = outp + (size_t)d * 121;
    int deg = g_deg[d];
    if (deg > CAP_) deg = CAP_;

    if (deg == 0) {
#pragma unroll
        for (int k = 0; k < 4; k++) {
            int c = lane + 32 * k;
            if (c < 121) out[c] = 0.f;
        }
        return;
    }

    const float NEG = -3.0e38f;
    float4 erv = *(const float4*)(g_er + (size_t)d * 4);
    int   s  = 0;
    float e0 = NEG, e1 = NEG, e2 = NEG, e3 = NEG;
    if (lane < deg) {
        s = g_bkt[(size_t)d * CAP_ + lane];
        float4 elv = *(const float4*)(g_el + (size_t)s * 4);
        e0 = elv.x + erv.x; e0 = (e0 >= 0.f) ? e0 : 0.2f * e0;
        e1 = elv.y + erv.y; e1 = (e1 >= 0.f) ? e1 : 0.2f * e1;
        e2 = elv.z + erv.z; e2 = (e2 >= 0.f) ? e2 : 0.2f * e2;
        e3 = elv.w + erv.w; e3 = (e3 >= 0.f) ? e3 : 0.2f * e3;
    }
    float m0 = wmax(e0), m1 = wmax(e1), m2 = wmax(e2), m3 = wmax(e3);
    float x0 = (lane < deg) ? expf(e0 - m0) : 0.f;
    float x1 = (lane < deg) ? expf(e1 - m1) : 0.f;
    float x2 = (lane < deg) ? expf(e2 - m2) : 0.f;
    float x3 = (lane < deg) ? expf(e3 - m3) : 0.f;
    float a0 = x0 / wsum(x0);
    float a1 = x1 / wsum(x1);
    float a2 = x2 / wsum(x2);
    float a3 = x3 / wsum(x3);

    // acc over j = lane + 32k, k < 16 (j < 484); head = j/121
    float acc[16];
#pragma unroll
    for (int k = 0; k < 16; k++) acc[k] = 0.f;

    for (int i = 0; i < deg; i++) {
        int   si = __shfl_sync(0xffffffffu, s, i);
        float b0 = __shfl_sync(0xffffffffu, a0, i);
        float b1 = __shfl_sync(0xffffffffu, a1, i);
        float b2 = __shfl_sync(0xffffffffu, a2, i);
        float b3 = __shfl_sync(0xffffffffu, a3, i);
        const float* F = g_feat + (size_t)si * 484;
#pragma unroll
        for (int k = 0; k < 16; k++) {
            int j = lane + 32 * k;
            if (j < 484) {
                float w = (j < 121) ? b0 : (j < 242) ? b1 : (j < 363) ? b2 : b3;
                acc[k] = fmaf(w, F[j], acc[k]);
            }
        }
    }

    // stage to smem, then head-mean
#pragma unroll
    for (int k = 0; k < 16; k++) {
        int j = lane + 32 * k;
        if (j < 484) sm[warp][j] = acc[k];
    }
    __syncwarp();
#pragma unroll
    for (int k = 0; k < 4; k++) {
        int c = lane + 32 * k;
        if (c < 121)
            out[c] = 0.25f * (sm[warp][c] + sm[warp][c + 121] +
                              sm[warp][c + 242] + sm[warp][c + 363]);
    }
}

// ---------------------------------------------------------------------------
// Launch
// ---------------------------------------------------------------------------
extern "C" void kernel_launch(void* const* d_in, const int* in_sizes, int n_in,
                              void* d_out, int out_size)
{
    const float* h   = (const float*)d_in[0];
    const int*   src = (const int*)d_in[1];
    const int*   dst = (const int*)d_in[2];
    const float* W [3] = {(const float*)d_in[3], (const float*)d_in[6], (const float*)d_in[9]};
    const float* al[3] = {(const float*)d_in[4], (const float*)d_in[7], (const float*)d_in[10]};
    const float* ar[3] = {(const float*)d_in[5], (const float*)d_in[8], (const float*)d_in[11]};
    float* out = (float*)d_out;

    void* p;
    cudaGetSymbolAddress(&p, g_feat); float* feat = (float*)p;
    cudaGetSymbolAddress(&p, g_x);    float* x    = (float*)p;

    const int T = 256;

    // ---- build per-dst src buckets (graph is reused by all 3 layers) ----
    deg_zero_kernel<<<(N_ + T - 1) / T, T>>>();
    scatter_kernel<<<(E_ + T - 1) / T, T>>>(src, dst);

    // shim launch (slot 3) so the first GEMM lands in the ncu capture slot (4):
    // zero d_out (fully overwritten later; harmless, ~6 us)
    {
        int n4 = (N_ * 121) / 4;   // 6,050,000 / 4 — integer, 16B-aligned buffer
        zero4_kernel<<<(n4 + T - 1) / T, T>>>((float4*)out, n4);
    }

    for (int L = 0; L < 3; L++) {
        const int HD = (L == 2) ? 484 : 256;
        const int D  = (L == 2) ? 121 : 64;
        const float* A = (L == 0) ? h : x;

        // feat = A @ W   (TF32x3 tensor cores)
        dim3 gg((HD + 127) / 128, (N_ + 127) / 128);
        gemm_tf32_kernel<<<gg, T>>>(A, W[L], feat, N_, HD);

        // attention logits per node
        elr_kernel<<<((N_ * H_ * 32) + T - 1) / T, T>>>(al[L], ar[L], D);

        // fused gather: softmax + aggregation + activation
        int blocks = (N_ * 32 + T - 1) / T;
        if (L == 2) gat_gather484_kernel<<<blocks, T>>>(out);
        else        gat_gather256_kernel<<<blocks, T>>>();
    }
}

// round 15
// speedup vs baseline: 2.0592x; 1.5030x over previous
#include <cuda_runtime.h>
#include <cstdint>

// ---------------------------------------------------------------------------
// GAT (3 layers) on GB300 — 1xTF32 tensor-core GEMM + gather-based edge softmax
//   N=50000 nodes, E=400000 edges, H=4 heads, D=64/64/121, Fin=256 each layer
//   GEMM: tf32 mma, cvt hoisted to smem store, register-prefetch pipeline.
//   Aggregation: warp-per-dst gather over per-dst src buckets (avg degree 8).
//   (Third submission of this source — R12/R13 benches died on infra:
//    device-busy at harness init, then container provisioning failure.)
// ---------------------------------------------------------------------------

constexpr int N_   = 50000;
constexpr int E_   = 400000;
constexpr int H_   = 4;
constexpr int CAP_ = 64;     // bucket capacity per dst (Poisson(8); P(>64) ~ 0)

// Scratch (allocation-free: __device__ globals)
__device__ __align__(16) float g_feat[(size_t)N_ * 484];  // W-projected features
__device__ __align__(16) float g_x   [(size_t)N_ * 256];  // activated layer output
__device__ __align__(16) float g_el  [N_ * H_];
__device__ __align__(16) float g_er  [N_ * H_];
__device__ int  g_deg[N_];
__device__ int  g_bkt[(size_t)N_ * CAP_];                 // src ids grouped by dst

// ---------------------------------------------------------------------------
// Utility
// ---------------------------------------------------------------------------
__global__ void zero4_kernel(float4* __restrict__ p, int n4) {
    int t = blockIdx.x * blockDim.x + threadIdx.x;
    if (t < n4) p[t] = make_float4(0.f, 0.f, 0.f, 0.f);
}

__global__ void deg_zero_kernel() {
    int t = blockIdx.x * blockDim.x + threadIdx.x;
    if (t < N_) g_deg[t] = 0;
}

__global__ void scatter_kernel(const int* __restrict__ src, const int* __restrict__ dst) {
    int e = blockIdx.x * blockDim.x + threadIdx.x;
    if (e >= E_) return;
    int d = dst[e];
    int slot = atomicAdd(&g_deg[d], 1);
    if (slot < CAP_) g_bkt[(size_t)d * CAP_ + slot] = src[e];
}

// ---------------------------------------------------------------------------
// 1xTF32 tensor-core GEMM: C[M,Nc] = A[M,256] * B[256,Nc]
// Block tile 128x128, BK=32, 256 threads (8 warps, each 64x32).
// tf32 conversion (cvt.rna) happens at smem-store time; inner loop is LDS+MMA.
// Register prefetch of tile k+1 overlaps global loads with compute on tile k.
// ---------------------------------------------------------------------------
__device__ __forceinline__ unsigned to_tf32(float x) {
    unsigned r;
    asm("cvt.rna.tf32.f32 %0, %1;" : "=r"(r) : "f"(x));
    return r;
}

__device__ __forceinline__ void mma_tf32(float c[4], const unsigned a[4],
                                         unsigned b0, unsigned b1) {
    asm volatile(
        "mma.sync.aligned.m16n8k8.row.col.f32.tf32.tf32.f32 "
        "{%0,%1,%2,%3}, {%4,%5,%6,%7}, {%8,%9}, {%0,%1,%2,%3};"
        : "+f"(c[0]), "+f"(c[1]), "+f"(c[2]), "+f"(c[3])
        : "r"(a[0]), "r"(a[1]), "r"(a[2]), "r"(a[3]), "r"(b0), "r"(b1));
}

__global__ __launch_bounds__(256) void gemm_tf32_kernel(
    const float* __restrict__ A, const float* __restrict__ B, float* __restrict__ C,
    int M, int Nc)
{
    constexpr int K = 256, BM = 128, BN = 128, BK = 32;
    __shared__ unsigned As[BK][BM + 4];   // [k][m], tf32-encoded
    __shared__ unsigned Bs[BK][BN + 4];   // [k][n], tf32-encoded

    const int tid  = threadIdx.x;
    const int lane = tid & 31;
    const int wid  = tid >> 5;
    const int gid  = lane >> 2;    // 0..7
    const int tig  = lane & 3;     // 0..3
    const int wm   = (wid & 1) * 64;
    const int wn   = (wid >> 1) * 32;
    const int m0   = blockIdx.y * BM;
    const int n0   = blockIdx.x * BN;

    float c[4][4][4];
#pragma unroll
    for (int i = 0; i < 4; i++)
#pragma unroll
        for (int j = 0; j < 4; j++)
#pragma unroll
            for (int k = 0; k < 4; k++) c[i][j][k] = 0.f;

    float4 pa[4], pb[4];

    // ---- prologue: prefetch tile 0 into registers ----
#pragma unroll
    for (int r = 0; r < 4; r++) {
        int i   = tid + r * 256;
        int row = i >> 3;
        int gm  = m0 + row;
        pa[r] = make_float4(0.f, 0.f, 0.f, 0.f);
        if (gm < M) pa[r] = *(const float4*)(A + (size_t)gm * K + (i & 7) * 4);
    }
#pragma unroll
    for (int r = 0; r < 4; r++) {
        int i   = tid + r * 256;
        int row = i >> 5;
        int gn  = n0 + (i & 31) * 4;
        pb[r] = make_float4(0.f, 0.f, 0.f, 0.f);
        if (gn < Nc) pb[r] = *(const float4*)(B + (size_t)row * Nc + gn);
    }

    for (int k0 = 0; k0 < K; k0 += BK) {
        // ---- store prefetched tile to smem (convert to tf32 here) ----
#pragma unroll
        for (int r = 0; r < 4; r++) {
            int i   = tid + r * 256;
            int row = i >> 3;
            int c4  = (i & 7) * 4;
            As[c4 + 0][row] = to_tf32(pa[r].x);
            As[c4 + 1][row] = to_tf32(pa[r].y);
            As[c4 + 2][row] = to_tf32(pa[r].z);
            As[c4 + 3][row] = to_tf32(pa[r].w);
        }
#pragma unroll
        for (int r = 0; r < 4; r++) {
            int i   = tid + r * 256;
            int row = i >> 5;
            int c4  = (i & 31) * 4;
            uint4 v;
            v.x = to_tf32(pb[r].x); v.y = to_tf32(pb[r].y);
            v.z = to_tf32(pb[r].z); v.w = to_tf32(pb[r].w);
            *(uint4*)&Bs[row][c4] = v;
        }
        __syncthreads();

        // ---- prefetch next tile into registers (overlaps compute below) ----
        if (k0 + BK < K) {
#pragma unroll
            for (int r = 0; r < 4; r++) {
                int i   = tid + r * 256;
                int row = i >> 3;
                int gm  = m0 + row;
                pa[r] = make_float4(0.f, 0.f, 0.f, 0.f);
                if (gm < M) pa[r] = *(const float4*)(A + (size_t)gm * K + k0 + BK + (i & 7) * 4);
            }
#pragma unroll
            for (int r = 0; r < 4; r++) {
                int i   = tid + r * 256;
                int row = i >> 5;
                int gn  = n0 + (i & 31) * 4;
                pb[r] = make_float4(0.f, 0.f, 0.f, 0.f);
                if (gn < Nc) pb[r] = *(const float4*)(B + (size_t)(k0 + BK + row) * Nc + gn);
            }
        }

        // ---- mainloop: pure LDS + MMA ----
#pragma unroll
        for (int kk = 0; kk < BK; kk += 8) {
            unsigned a[4][4];
#pragma unroll
            for (int mt = 0; mt < 4; mt++) {
                int r0 = wm + mt * 16 + gid;
                a[mt][0] = As[kk + tig    ][r0];
                a[mt][1] = As[kk + tig    ][r0 + 8];
                a[mt][2] = As[kk + tig + 4][r0];
                a[mt][3] = As[kk + tig + 4][r0 + 8];
            }
#pragma unroll
            for (int nt = 0; nt < 4; nt++) {
                int cn = wn + nt * 8 + gid;
                unsigned b0 = Bs[kk + tig    ][cn];
                unsigned b1 = Bs[kk + tig + 4][cn];
#pragma unroll
                for (int mt = 0; mt < 4; mt++)
                    mma_tf32(c[mt][nt], a[mt], b0, b1);
            }
        }
        __syncthreads();
    }

#pragma unroll
    for (int mt = 0; mt < 4; mt++) {
        int r0 = m0 + wm + mt * 16 + gid;
#pragma unroll
        for (int nt = 0; nt < 4; nt++) {
            int cn = n0 + wn + nt * 8 + tig * 2;
            if (cn < Nc) {
                if (r0 < M)
                    *(float2*)(C + (size_t)r0 * Nc + cn) =
                        make_float2(c[mt][nt][0], c[mt][nt][1]);
                if (r0 + 8 < M)
                    *(float2*)(C + (size_t)(r0 + 8) * Nc + cn) =
                        make_float2(c[mt][nt][2], c[mt][nt][3]);
            }
        }
    }
}

// ---------------------------------------------------------------------------
// el/er: per (node, head) dot products with attention vectors. Warp per (n,h).
// ---------------------------------------------------------------------------
__global__ void elr_kernel(const float* __restrict__ al, const float* __restrict__ ar, int D) {
    int gw   = (blockIdx.x * blockDim.x + threadIdx.x) >> 5;
    int lane = threadIdx.x & 31;
    if (gw >= N_ * H_) return;
    int n = gw >> 2, h = gw & 3;
    const float* f = g_feat + (size_t)n * (H_ * D) + h * D;
    const float* a = al + h * D;
    const float* b = ar + h * D;
    float sl = 0.f, sr = 0.f;
    for (int d = lane; d < D; d += 32) {
        float v = f[d];
        sl = fmaf(v, a[d], sl);
        sr = fmaf(v, b[d], sr);
    }
#pragma unroll
    for (int o = 16; o; o >>= 1) {
        sl += __shfl_xor_sync(0xffffffffu, sl, o);
        sr += __shfl_xor_sync(0xffffffffu, sr, o);
    }
    if (lane == 0) { g_el[gw] = sl; g_er[gw] = sr; }
}

// ---------------------------------------------------------------------------
// Warp-reduce helpers
// ---------------------------------------------------------------------------
__device__ __forceinline__ float wmax(float v) {
#pragma unroll
    for (int o = 16; o; o >>= 1) v = fmaxf(v, __shfl_xor_sync(0xffffffffu, v, o));
    return v;
}
__device__ __forceinline__ float wsum(float v) {
#pragma unroll
    for (int o = 16; o; o >>= 1) v += __shfl_xor_sync(0xffffffffu, v, o);
    return v;
}

// ---------------------------------------------------------------------------
// Fused gather kernel, layers 1/2 (HD=256, D=64): warp per dst node.
// ---------------------------------------------------------------------------
__global__ __launch_bounds__(256) void gat_gather256_kernel() {
    const int d    = (blockIdx.x * blockDim.x + threadIdx.x) >> 5;
    const int lane = threadIdx.x & 31;
    if (d >= N_) return;

    float* out = g_x + (size_t)d * 256;
    int deg = g_deg[d];
    if (deg > CAP_) deg = CAP_;

    if (deg == 0) {
        *(float4*)(out + lane * 4)       = make_float4(0.f, 0.f, 0.f, 0.f);
        *(float4*)(out + 128 + lane * 4) = make_float4(0.f, 0.f, 0.f, 0.f);
        return;
    }

    const float NEG = -3.0e38f;
    float4 erv = *(const float4*)(g_er + (size_t)d * 4);
    int   s  = 0;
    float e0 = NEG, e1 = NEG, e2 = NEG, e3 = NEG;
    if (lane < deg) {
        s = g_bkt[(size_t)d * CAP_ + lane];
        float4 elv = *(const float4*)(g_el + (size_t)s * 4);
        e0 = elv.x + erv.x; e0 = (e0 >= 0.f) ? e0 : 0.2f * e0;
        e1 = elv.y + erv.y; e1 = (e1 >= 0.f) ? e1 : 0.2f * e1;
        e2 = elv.z + erv.z; e2 = (e2 >= 0.f) ? e2 : 0.2f * e2;
        e3 = elv.w + erv.w; e3 = (e3 >= 0.f) ? e3 : 0.2f * e3;
    }
    float m0 = wmax(e0), m1 = wmax(e1), m2 = wmax(e2), m3 = wmax(e3);
    float x0 = (lane < deg) ? expf(e0 - m0) : 0.f;
    float x1 = (lane < deg) ? expf(e1 - m1) : 0.f;
    float x2 = (lane < deg) ? expf(e2 - m2) : 0.f;
    float x3 = (lane < deg) ? expf(e3 - m3) : 0.f;
    float a0 = x0 / wsum(x0);
    float a1 = x1 / wsum(x1);
    float a2 = x2 / wsum(x2);
    float a3 = x3 / wsum(x3);

    float4 acc0 = make_float4(0.f, 0.f, 0.f, 0.f);
    float4 acc1 = make_float4(0.f, 0.f, 0.f, 0.f);
    const bool hi16 = (lane >= 16);

    for (int i = 0; i < deg; i++) {
        int   si = __shfl_sync(0xffffffffu, s, i);
        float b0 = __shfl_sync(0xffffffffu, a0, i);
        float b1 = __shfl_sync(0xffffffffu, a1, i);
        float b2 = __shfl_sync(0xffffffffu, a2, i);
        float b3 = __shfl_sync(0xffffffffu, a3, i);
        float wa = hi16 ? b1 : b0;
        float wb = hi16 ? b3 : b2;
        const float* F = g_feat + (size_t)si * 256;
        float4 f0 = *(const float4*)(F + lane * 4);
        float4 f1 = *(const float4*)(F + 128 + lane * 4);
        acc0.x = fmaf(wa, f0.x, acc0.x); acc0.y = fmaf(wa, f0.y, acc0.y);
        acc0.z = fmaf(wa, f0.z, acc0.z); acc0.w = fmaf(wa, f0.w, acc0.w);
        acc1.x = fmaf(wb, f1.x, acc1.x); acc1.y = fmaf(wb, f1.y, acc1.y);
        acc1.z = fmaf(wb, f1.z, acc1.z); acc1.w = fmaf(wb, f1.w, acc1.w);
    }

    float4 o0, o1;
    o0.x = acc0.x > 0.f ? acc0.x : expm1f(acc0.x);
    o0.y = acc0.y > 0.f ? acc0.y : expm1f(acc0.y);
    o0.z = acc0.z > 0.f ? acc0.z : expm1f(acc0.z);
    o0.w = acc0.w > 0.f ? acc0.w : expm1f(acc0.w);
    o1.x = acc1.x > 0.f ? acc1.x : expm1f(acc1.x);
    o1.y = acc1.y > 0.f ? acc1.y : expm1f(acc1.y);
    o1.z = acc1.z > 0.f ? acc1.z : expm1f(acc1.z);
    o1.w = acc1.w > 0.f ? acc1.w : expm1f(acc1.w);
    *(float4*)(out + lane * 4)       = o0;
    *(float4*)(out + 128 + lane * 4) = o1;
}

// ---------------------------------------------------------------------------
// Fused gather kernel, layer 3 (HD=484, D=121): warp per dst node.
// ---------------------------------------------------------------------------
__global__ __launch_bounds__(256) void gat_gather484_kernel(float* __restrict__ outp) {
    __shared__ float sm[8][484];
    const int d    = (blockIdx.x * blockDim.x + threadIdx.x) >> 5;
    const int lane = threadIdx.x & 31;
    const int warp = (threadIdx.x >> 5);
    if (d >= N_) return;

    float* out = outp + (size_t)d * 121;
    int deg = g_deg[d];
    if (deg > CAP_) deg = CAP_;

    if (deg == 0) {
#pragma unroll
        for (int k = 0; k < 4; k++) {
            int c = lane + 32 * k;
            if (c < 121) out[c] = 0.f;
        }
        return;
    }

    const float NEG = -3.0e38f;
    float4 erv = *(const float4*)(g_er + (size_t)d * 4);
    int   s  = 0;
    float e0 = NEG, e1 = NEG, e2 = NEG, e3 = NEG;
    if (lane < deg) {
        s = g_bkt[(size_t)d * CAP_ + lane];
        float4 elv = *(const float4*)(g_el + (size_t)s * 4);
        e0 = elv.x + erv.x; e0 = (e0 >= 0.f) ? e0 : 0.2f * e0;
        e1 = elv.y + erv.y; e1 = (e1 >= 0.f) ? e1 : 0.2f * e1;
        e2 = elv.z + erv.z; e2 = (e2 >= 0.f) ? e2 : 0.2f * e2;
        e3 = elv.w + erv.w; e3 = (e3 >= 0.f) ? e3 : 0.2f * e3;
    }
    float m0 = wmax(e0), m1 = wmax(e1), m2 = wmax(e2), m3 = wmax(e3);
    float x0 = (lane < deg) ? expf(e0 - m0) : 0.f;
    float x1 = (lane < deg) ? expf(e1 - m1) : 0.f;
    float x2 = (lane < deg) ? expf(e2 - m2) : 0.f;
    float x3 = (lane < deg) ? expf(e3 - m3) : 0.f;
    float a0 = x0 / wsum(x0);
    float a1 = x1 / wsum(x1);
    float a2 = x2 / wsum(x2);
    float a3 = x3 / wsum(x3);

    float acc[16];
#pragma unroll
    for (int k = 0; k < 16; k++) acc[k] = 0.f;

    for (int i = 0; i < deg; i++) {
        int   si = __shfl_sync(0xffffffffu, s, i);
        float b0 = __shfl_sync(0xffffffffu, a0, i);
        float b1 = __shfl_sync(0xffffffffu, a1, i);
        float b2 = __shfl_sync(0xffffffffu, a2, i);
        float b3 = __shfl_sync(0xffffffffu, a3, i);
        const float* F = g_feat + (size_t)si * 484;
#pragma unroll
        for (int k = 0; k < 16; k++) {
            int j = lane + 32 * k;
            if (j < 484) {
                float w = (j < 121) ? b0 : (j < 242) ? b1 : (j < 363) ? b2 : b3;
                acc[k] = fmaf(w, F[j], acc[k]);
            }
        }
    }

#pragma unroll
    for (int k = 0; k < 16; k++) {
        int j = lane + 32 * k;
        if (j < 484) sm[warp][j] = acc[k];
    }
    __syncwarp();
#pragma unroll
    for (int k = 0; k < 4; k++) {
        int c = lane + 32 * k;
        if (c < 121)
            out[c] = 0.25f * (sm[warp][c] + sm[warp][c + 121] +
                              sm[warp][c + 242] + sm[warp][c + 363]);
    }
}

// ---------------------------------------------------------------------------
// Launch
// ---------------------------------------------------------------------------
extern "C" void kernel_launch(void* const* d_in, const int* in_sizes, int n_in,
                              void* d_out, int out_size)
{
    const float* h   = (const float*)d_in[0];
    const int*   src = (const int*)d_in[1];
    const int*   dst = (const int*)d_in[2];
    const float* W [3] = {(const float*)d_in[3], (const float*)d_in[6], (const float*)d_in[9]};
    const float* al[3] = {(const float*)d_in[4], (const float*)d_in[7], (const float*)d_in[10]};
    const float* ar[3] = {(const float*)d_in[5], (const float*)d_in[8], (const float*)d_in[11]};
    float* out = (float*)d_out;

    void* p;
    cudaGetSymbolAddress(&p, g_feat); float* feat = (float*)p;
    cudaGetSymbolAddress(&p, g_x);    float* x    = (float*)p;

    const int T = 256;

    // ---- build per-dst src buckets (graph is reused by all 3 layers) ----
    deg_zero_kernel<<<(N_ + T - 1) / T, T>>>();
    scatter_kernel<<<(E_ + T - 1) / T, T>>>(src, dst);

    // shim launch (slot 3) so the first GEMM lands in the ncu capture slot (4)
    {
        int n4 = (N_ * 121) / 4;
        zero4_kernel<<<(n4 + T - 1) / T, T>>>((float4*)out, n4);
    }

    for (int L = 0; L < 3; L++) {
        const int HD = (L == 2) ? 484 : 256;
        const int D  = (L == 2) ? 121 : 64;
        const float* A = (L == 0) ? h : x;

        // feat = A @ W   (1xTF32 tensor cores)
        dim3 gg((HD + 127) / 128, (N_ + 127) / 128);
        gemm_tf32_kernel<<<gg, T>>>(A, W[L], feat, N_, HD);

        // attention logits per node
        elr_kernel<<<((N_ * H_ * 32) + T - 1) / T, T>>>(al[L], ar[L], D);

        // fused gather: softmax + aggregation + activation
        int blocks = (N_ * 32 + T - 1) / T;
        if (L == 2) gat_gather484_kernel<<<blocks, T>>>(out);
        else        gat_gather256_kernel<<<blocks, T>>>();
    }
}